// round 6
// baseline (speedup 1.0000x reference)
#include <cuda_runtime.h>

// ============================================================================
// TorusConv3D via FFT diagonalization (round 5, resubmitted after infra fail).
// Round-5: occupancy / wave-balance pass.
//  - FFT kernels use 8-column tiles (32 KB smem): fwd grid 256->512,
//    ifft grid 128->256. More CTAs/SM, finer wave granularity.
//  - Pointwise splits the b-dimension across 2 blocks per frequency
//    (grid 260->520, ~50 KB smem, 4 CTAs/SM -> single resident wave).
// Math identical to round 4 (real-pair packed spectra, Hermitian canonical
// frequencies, f32x2 packed FMA GEMM).
// ============================================================================

#define R2 0.70710678118654752440f

// Packed spectra: g_Xp[k*2048 + b*32 + j], g_Wp[k*2048 + f*32 + j],
//                 g_Z [k*2048 + b*32 + fp]
__device__ float2 g_Xp[512 * 2048];
__device__ float2 g_Wp[512 * 2048];
__device__ float2 g_Z[512 * 2048];

// ---------------------------------------------------------------------------
// Radix-2 DIT 8-point FFT, in place. Forward = e^{-2pi i nk/8}; INV conjugates.
// ---------------------------------------------------------------------------
__device__ __forceinline__ float2 cadd(float2 a, float2 b) { return make_float2(a.x + b.x, a.y + b.y); }
__device__ __forceinline__ float2 csub(float2 a, float2 b) { return make_float2(a.x - b.x, a.y - b.y); }
template <int INV>
__device__ __forceinline__ float2 mulmi(float2 a) {
    return INV ? make_float2(-a.y, a.x) : make_float2(a.y, -a.x);
}
template <int INV>
__device__ __forceinline__ float2 mulw1(float2 a) {
    return INV ? make_float2(R2 * (a.x - a.y), R2 * (a.y + a.x))
               : make_float2(R2 * (a.x + a.y), R2 * (a.y - a.x));
}
template <int INV>
__device__ __forceinline__ float2 mulw3(float2 a) {
    return INV ? make_float2(R2 * (-a.x - a.y), R2 * (a.x - a.y))
               : make_float2(R2 * (a.y - a.x), R2 * (-a.x - a.y));
}

template <int INV>
__device__ __forceinline__ void fft8(float2* v) {
    float2 t0 = cadd(v[0], v[4]), t1 = csub(v[0], v[4]);
    float2 t2 = cadd(v[2], v[6]), t3 = csub(v[2], v[6]);
    float2 t4 = cadd(v[1], v[5]), t5 = csub(v[1], v[5]);
    float2 t6 = cadd(v[3], v[7]), t7 = csub(v[3], v[7]);
    float2 a0 = cadd(t0, t2), a1 = csub(t0, t2);
    float2 m3 = mulmi<INV>(t3);
    float2 a2 = cadd(t1, m3), a3 = csub(t1, m3);
    float2 b0 = cadd(t4, t6), b1 = csub(t4, t6);
    float2 m7 = mulmi<INV>(t7);
    float2 b2 = cadd(t5, m7), b3 = csub(t5, m7);
    float2 mb1 = mulmi<INV>(b1);
    float2 w1 = mulw1<INV>(b2);
    float2 w3 = mulw3<INV>(b3);
    v[0] = cadd(a0, b0); v[4] = csub(a0, b0);
    v[2] = cadd(a1, mb1); v[6] = csub(a1, mb1);
    v[1] = cadd(a2, w1); v[5] = csub(a2, w1);
    v[3] = cadd(a3, w3); v[7] = csub(a3, w3);
}

// ---------------------------------------------------------------------------
// Packed f32x2 helpers.
// ---------------------------------------------------------------------------
__device__ __forceinline__ unsigned long long pack2(float lo, float hi) {
    unsigned long long r;
    asm("mov.b64 %0, {%1, %2};" : "=l"(r) : "f"(lo), "f"(hi));
    return r;
}
__device__ __forceinline__ unsigned long long fma2(unsigned long long a, unsigned long long b,
                                                   unsigned long long c) {
    unsigned long long d;
    asm("fma.rn.f32x2 %0, %1, %2, %3;" : "=l"(d) : "l"(a), "l"(b), "l"(c));
    return d;
}
__device__ __forceinline__ float2 unpack2(unsigned long long v) {
    float lo, hi;
    asm("mov.b64 {%0, %1}, %2;" : "=f"(lo), "=f"(hi) : "l"(v));
    return make_float2(lo, hi);
}

// ---------------------------------------------------------------------------
// Forward packed FFT, 8-column tiles. One block: one row (b or f) + 8 packed
// columns. smem V[s*8 + c] (32 KB), s = x*64+y*8+z. 256 threads: c = tid&7,
// pp = tid>>3 (32 line slots, 64 lines per phase -> 2 iters).
// Blocks [0,256) -> inputs->Xp, [256,512) -> kernel->Wp.
// ---------------------------------------------------------------------------
__global__ void __launch_bounds__(256)
fft3d_fwd_packed(const float* __restrict__ inA, const float* __restrict__ inB,
                 float2* __restrict__ outA, float2* __restrict__ outB) {
    extern __shared__ float2 V[];
    int blk = blockIdx.x;
    const float* in;
    float2* out;
    long rowStride, sStride;
    if (blk < 256) { in = inA; out = outA; rowStride = 32768; sStride = 64; }
    else           { blk -= 256; in = inB; out = outB; rowStride = 64; sStride = 4096; }
    const int row = blk >> 2, j0 = (blk & 3) * 8;
    const int tid = threadIdx.x;
    const int c = tid & 7, pp = tid >> 3;

    const float* base = in + (long)row * rowStride + 2 * (j0 + c);
    float2 buf[8];

    // Phase 1: z-axis fused with packed global load. t = (x,y), s = 8t + z.
    for (int m = 0; m < 2; ++m) {
        const int t = pp + 32 * m;
#pragma unroll
        for (int z = 0; z < 8; ++z)
            buf[z] = *(const float2*)(base + (long)(8 * t + z) * sStride);
        fft8<0>(buf);
#pragma unroll
        for (int z = 0; z < 8; ++z) V[(8 * t + z) * 8 + c] = buf[z];
    }
    __syncthreads();

    // Phase 2: y-axis through smem. t = (x,z). stride 8*8 = 64.
    for (int m = 0; m < 2; ++m) {
        const int t = pp + 32 * m;
        const int b0 = (t >> 3) * 512 + (t & 7) * 8 + c;
#pragma unroll
        for (int y = 0; y < 8; ++y) buf[y] = V[b0 + y * 64];
        fft8<0>(buf);
#pragma unroll
        for (int y = 0; y < 8; ++y) V[b0 + y * 64] = buf[y];
    }
    __syncthreads();

    // Phase 3: x-axis fused with global store. t = (ky,kz). stride 512.
    float2* og = out + row * 32 + j0 + c;
    for (int m = 0; m < 2; ++m) {
        const int t = pp + 32 * m;
#pragma unroll
        for (int x = 0; x < 8; ++x) buf[x] = V[t * 8 + c + x * 512];
        fft8<0>(buf);
#pragma unroll
        for (int x = 0; x < 8; ++x) og[(long)(x * 64 + t) * 2048] = buf[x];
    }
}

// ---------------------------------------------------------------------------
// Hermitian pointwise complex GEMM, canonical freqs x 2 b-halves (520 blocks).
// Fill: unpack packed spectra using (k,-k). Drain: pack f-pairs via shfl.
// ---------------------------------------------------------------------------
__global__ void __launch_bounds__(256)
pointwise_kernel(const float2* __restrict__ Xp, const float2* __restrict__ Wp,
                 float2* __restrict__ Zh) {
    const int rank = blockIdx.x >> 1;
    const int b0r = (blockIdx.x & 1) * 32;  // b-half base
    int kx, ky, kz;
    if (rank < 192) {
        kx = 1 + rank / 64; const int r = rank & 63; ky = r >> 3; kz = r & 7;
    } else if (rank < 240) {
        const int r = rank - 192; kx = (r / 24) * 4;
        const int r2 = r % 24; ky = 1 + r2 / 8; kz = r2 & 7;
    } else {
        const int r = rank - 240; kx = (r / 10) * 4;
        const int r2 = r % 10; ky = (r2 / 5) * 4; kz = r2 % 5;
    }
    const int k = (kx << 6) | (ky << 3) | kz;
    const int neg = (((8 - kx) & 7) << 6) | (((8 - ky) & 7) << 3) | ((8 - kz) & 7);

    extern __shared__ float2 sm[];
    float2* As = sm;            // [c][b32], stride 33
    float2* Bs = sm + 64 * 33;  // [c][f],   stride 65
    const int tid = threadIdx.x;

    const float2* xk = Xp + (long)k * 2048 + b0r * 32;
    const float2* xn = Xp + (long)neg * 2048 + b0r * 32;
    const float2* wk = Wp + (long)k * 2048;
    const float2* wn = Wp + (long)neg * 2048;
    // A: 32 rows x 32 packed pairs = 1024
    for (int i = tid; i < 1024; i += 256) {
        const int j = i & 31, rowi = i >> 5;
        const int c0 = 2 * j, c1 = 2 * j + 1;
        const float2 Pk = xk[i], Pn = xn[i];
        As[c0 * 33 + rowi] = make_float2(0.5f * (Pk.x + Pn.x), 0.5f * (Pk.y - Pn.y));
        As[c1 * 33 + rowi] = make_float2(0.5f * (Pk.y + Pn.y), 0.5f * (Pn.x - Pk.x));
    }
    // B: 64 rows x 32 packed pairs = 2048
    for (int i = tid; i < 2048; i += 256) {
        const int j = i & 31, rowi = i >> 5;
        const int c0 = 2 * j, c1 = 2 * j + 1;
        const float2 Pk = wk[i], Pn = wn[i];
        Bs[c0 * 65 + rowi] = make_float2(0.5f * (Pk.x + Pn.x), 0.5f * (Pk.y - Pn.y));
        Bs[c1 * 65 + rowi] = make_float2(0.5f * (Pk.y + Pn.y), 0.5f * (Pn.x - Pk.x));
    }
    __syncthreads();

    const int ft = tid & 15;   // f = ft + 16j
    const int bt = tid >> 4;   // local b = bt, bt+16
    unsigned long long acc[2][4];
#pragma unroll
    for (int i = 0; i < 2; ++i)
#pragma unroll
        for (int j = 0; j < 4; ++j) acc[i][j] = 0ULL;

    unsigned long long axax[2], nay[2], bxy[4], byx[4];
#pragma unroll 2
    for (int cc = 0; cc < 64; ++cc) {
#pragma unroll
        for (int i = 0; i < 2; ++i) {
            const float2 t = As[cc * 33 + bt + 16 * i];
            axax[i] = pack2(t.x, t.x);
            nay[i] = pack2(-t.y, t.y);
        }
#pragma unroll
        for (int j = 0; j < 4; ++j) {
            const float2 t = Bs[cc * 65 + ft + 16 * j];
            bxy[j] = pack2(t.x, t.y);
            byx[j] = pack2(t.y, t.x);
        }
#pragma unroll
        for (int i = 0; i < 2; ++i)
#pragma unroll
            for (int j = 0; j < 4; ++j) {
                acc[i][j] = fma2(axax[i], bxy[j], acc[i][j]);  // (+ax*bx, +ax*by)
                acc[i][j] = fma2(nay[i], byx[j], acc[i][j]);   // (-ay*by, +ay*bx)
            }
    }

    // Drain: pack f-pairs. Even-ft lanes own fp = ft/2 + 8j.
    float2* zk = Zh + (long)k * 2048;
    float2* zn = Zh + (long)neg * 2048;
    const bool self = (k == neg);
    const bool even = (ft & 1) == 0;
    const int fp0 = ft >> 1;
#pragma unroll
    for (int i = 0; i < 2; ++i)
#pragma unroll
        for (int j = 0; j < 4; ++j) {
            const unsigned long long part = __shfl_xor_sync(0xffffffffu, acc[i][j], 1);
            if (even) {
                const float2 Y0 = unpack2(acc[i][j]);  // f = 2fp
                const float2 Y1 = unpack2(part);       // f = 2fp+1
                const int idx = (b0r + bt + 16 * i) * 32 + fp0 + 8 * j;
                zk[idx] = make_float2(Y0.x - Y1.y, Y0.y + Y1.x);
                if (!self) zn[idx] = make_float2(Y0.x + Y1.y, Y1.x - Y0.y);
            }
        }
}

// ---------------------------------------------------------------------------
// Inverse packed FFT + bias, 8-column tiles. One block per (b, 8 fp columns).
// IFFT(Y_{2f} + i Y_{2f+1}) = out_{2f} + i out_{2f+1}.
// ---------------------------------------------------------------------------
__global__ void __launch_bounds__(256)
ifft3d_packed(const float2* __restrict__ Zh, const float* __restrict__ bias,
              float* __restrict__ out) {
    extern __shared__ float2 V[];
    const int b = blockIdx.x >> 2, fp0 = (blockIdx.x & 3) * 8;
    const int tid = threadIdx.x;
    const int c = tid & 7, pp = tid >> 3;
    const float2 bv = ((const float2*)bias)[fp0 + c];

    const float2* yg = Zh + b * 32 + fp0 + c;
    float2 buf[8];

    // Phase 1: z-axis fused with load.
    for (int m = 0; m < 2; ++m) {
        const int t = pp + 32 * m;
#pragma unroll
        for (int z = 0; z < 8; ++z) buf[z] = yg[(long)(8 * t + z) * 2048];
        fft8<1>(buf);
#pragma unroll
        for (int z = 0; z < 8; ++z) V[(8 * t + z) * 8 + c] = buf[z];
    }
    __syncthreads();

    // Phase 2: y-axis.
    for (int m = 0; m < 2; ++m) {
        const int t = pp + 32 * m;
        const int b0 = (t >> 3) * 512 + (t & 7) * 8 + c;
#pragma unroll
        for (int y = 0; y < 8; ++y) buf[y] = V[b0 + y * 64];
        fft8<1>(buf);
#pragma unroll
        for (int y = 0; y < 8; ++y) V[b0 + y * 64] = buf[y];
    }
    __syncthreads();

    // Phase 3: x-axis fused with store (re -> 2fp, im -> 2fp+1, +bias).
    float2* og = (float2*)out + (long)b * 512 * 32 + fp0 + c;
    for (int m = 0; m < 2; ++m) {
        const int t = pp + 32 * m;
#pragma unroll
        for (int x = 0; x < 8; ++x) buf[x] = V[t * 8 + c + x * 512];
        fft8<1>(buf);
#pragma unroll
        for (int x = 0; x < 8; ++x)
            og[(long)(x * 64 + t) * 32] =
                make_float2(buf[x].x * (1.f / 512.f) + bv.x,
                            buf[x].y * (1.f / 512.f) + bv.y);
    }
}

// ---------------------------------------------------------------------------
extern "C" void kernel_launch(void* const* d_in, const int* in_sizes, int n_in,
                              void* d_out, int out_size) {
    const float* inputs = (const float*)d_in[0];
    const float* kern   = (const float*)d_in[1];
    const float* bias   = (const float*)d_in[2];
    float* out = (float*)d_out;

    float2 *Xp, *Wp, *Zh;
    cudaGetSymbolAddress((void**)&Xp, g_Xp);
    cudaGetSymbolAddress((void**)&Wp, g_Wp);
    cudaGetSymbolAddress((void**)&Zh, g_Z);

    const int smemFFT = 512 * 8 * (int)sizeof(float2);               // 32768 B
    const int smemPW  = (64 * 33 + 64 * 65) * (int)sizeof(float2);   // 50176 B
    cudaFuncSetAttribute(fft3d_fwd_packed, cudaFuncAttributeMaxDynamicSharedMemorySize, smemFFT);
    cudaFuncSetAttribute(ifft3d_packed,    cudaFuncAttributeMaxDynamicSharedMemorySize, smemFFT);
    cudaFuncSetAttribute(pointwise_kernel, cudaFuncAttributeMaxDynamicSharedMemorySize, smemPW);

    fft3d_fwd_packed<<<512, 256, smemFFT>>>(inputs, kern, Xp, Wp);
    pointwise_kernel<<<520, 256, smemPW>>>(Xp, Wp, Zh);
    ifft3d_packed<<<256, 256, smemFFT>>>(Zh, bias, out);
}

// round 7
// speedup vs baseline: 1.0715x; 1.0715x over previous
#include <cuda_runtime.h>

// ============================================================================
// TorusConv3D via FFT diagonalization (round 7).
// Round-7: round-4 structure (16-column tiles, proven coalescing) with
// 512-thread blocks everywhere: halves per-thread serial work, ~2x warps/SM
// on the grid-limited FFT stages; pointwise goes fully resident (260 CTAs,
// 3/SM) with a 2x4 tile per thread.
// ============================================================================

#define R2 0.70710678118654752440f

// Packed spectra: g_Xp[k*2048 + b*32 + j], g_Wp[k*2048 + f*32 + j],
//                 g_Z [k*2048 + b*32 + fp]
__device__ float2 g_Xp[512 * 2048];
__device__ float2 g_Wp[512 * 2048];
__device__ float2 g_Z[512 * 2048];

// ---------------------------------------------------------------------------
// Radix-2 DIT 8-point FFT, in place. Forward = e^{-2pi i nk/8}; INV conjugates.
// ---------------------------------------------------------------------------
__device__ __forceinline__ float2 cadd(float2 a, float2 b) { return make_float2(a.x + b.x, a.y + b.y); }
__device__ __forceinline__ float2 csub(float2 a, float2 b) { return make_float2(a.x - b.x, a.y - b.y); }
template <int INV>
__device__ __forceinline__ float2 mulmi(float2 a) {
    return INV ? make_float2(-a.y, a.x) : make_float2(a.y, -a.x);
}
template <int INV>
__device__ __forceinline__ float2 mulw1(float2 a) {
    return INV ? make_float2(R2 * (a.x - a.y), R2 * (a.y + a.x))
               : make_float2(R2 * (a.x + a.y), R2 * (a.y - a.x));
}
template <int INV>
__device__ __forceinline__ float2 mulw3(float2 a) {
    return INV ? make_float2(R2 * (-a.x - a.y), R2 * (a.x - a.y))
               : make_float2(R2 * (a.y - a.x), R2 * (-a.x - a.y));
}

template <int INV>
__device__ __forceinline__ void fft8(float2* v) {
    float2 t0 = cadd(v[0], v[4]), t1 = csub(v[0], v[4]);
    float2 t2 = cadd(v[2], v[6]), t3 = csub(v[2], v[6]);
    float2 t4 = cadd(v[1], v[5]), t5 = csub(v[1], v[5]);
    float2 t6 = cadd(v[3], v[7]), t7 = csub(v[3], v[7]);
    float2 a0 = cadd(t0, t2), a1 = csub(t0, t2);
    float2 m3 = mulmi<INV>(t3);
    float2 a2 = cadd(t1, m3), a3 = csub(t1, m3);
    float2 b0 = cadd(t4, t6), b1 = csub(t4, t6);
    float2 m7 = mulmi<INV>(t7);
    float2 b2 = cadd(t5, m7), b3 = csub(t5, m7);
    float2 mb1 = mulmi<INV>(b1);
    float2 w1 = mulw1<INV>(b2);
    float2 w3 = mulw3<INV>(b3);
    v[0] = cadd(a0, b0); v[4] = csub(a0, b0);
    v[2] = cadd(a1, mb1); v[6] = csub(a1, mb1);
    v[1] = cadd(a2, w1); v[5] = csub(a2, w1);
    v[3] = cadd(a3, w3); v[7] = csub(a3, w3);
}

// ---------------------------------------------------------------------------
// Packed f32x2 helpers.
// ---------------------------------------------------------------------------
__device__ __forceinline__ unsigned long long pack2(float lo, float hi) {
    unsigned long long r;
    asm("mov.b64 %0, {%1, %2};" : "=l"(r) : "f"(lo), "f"(hi));
    return r;
}
__device__ __forceinline__ unsigned long long fma2(unsigned long long a, unsigned long long b,
                                                   unsigned long long c) {
    unsigned long long d;
    asm("fma.rn.f32x2 %0, %1, %2, %3;" : "=l"(d) : "l"(a), "l"(b), "l"(c));
    return d;
}
__device__ __forceinline__ float2 unpack2(unsigned long long v) {
    float lo, hi;
    asm("mov.b64 {%0, %1}, %2;" : "=f"(lo), "=f"(hi) : "l"(v));
    return make_float2(lo, hi);
}

// ---------------------------------------------------------------------------
// Forward packed FFT, 16-column tiles, 512 threads. One block: one row (b or
// f) + 16 packed columns. smem V[s*16 + c] (64 KB), s = x*64+y*8+z.
// c = tid&15, pp = tid>>4 (32 line slots, 64 lines/phase -> 2 iters).
// Blocks [0,128) -> inputs->Xp, [128,256) -> kernel->Wp.
// ---------------------------------------------------------------------------
__global__ void __launch_bounds__(512)
fft3d_fwd_packed(const float* __restrict__ inA, const float* __restrict__ inB,
                 float2* __restrict__ outA, float2* __restrict__ outB) {
    extern __shared__ float2 V[];
    int blk = blockIdx.x;
    const float* in;
    float2* out;
    long rowStride, sStride;
    if (blk < 128) { in = inA; out = outA; rowStride = 32768; sStride = 64; }
    else           { blk -= 128; in = inB; out = outB; rowStride = 64; sStride = 4096; }
    const int row = blk >> 1, j0 = (blk & 1) * 16;
    const int tid = threadIdx.x;
    const int c = tid & 15, pp = tid >> 4;

    const float* base = in + (long)row * rowStride + 2 * (j0 + c);
    float2 buf[8];

    // Phase 1: z-axis fused with packed global load. t = (x,y), s = 8t + z.
#pragma unroll
    for (int m = 0; m < 2; ++m) {
        const int t = pp + 32 * m;
#pragma unroll
        for (int z = 0; z < 8; ++z)
            buf[z] = *(const float2*)(base + (long)(8 * t + z) * sStride);
        fft8<0>(buf);
#pragma unroll
        for (int z = 0; z < 8; ++z) V[(8 * t + z) * 16 + c] = buf[z];
    }
    __syncthreads();

    // Phase 2: y-axis through smem. t = (x,z). stride 8*16 = 128.
#pragma unroll
    for (int m = 0; m < 2; ++m) {
        const int t = pp + 32 * m;
        const int b0 = ((t >> 3) * 64 + (t & 7)) * 16 + c;
#pragma unroll
        for (int y = 0; y < 8; ++y) buf[y] = V[b0 + y * 128];
        fft8<0>(buf);
#pragma unroll
        for (int y = 0; y < 8; ++y) V[b0 + y * 128] = buf[y];
    }
    __syncthreads();

    // Phase 3: x-axis fused with global store. t = (ky,kz). stride 1024.
    float2* og = out + row * 32 + j0 + c;
#pragma unroll
    for (int m = 0; m < 2; ++m) {
        const int t = pp + 32 * m;
#pragma unroll
        for (int x = 0; x < 8; ++x) buf[x] = V[t * 16 + c + x * 1024];
        fft8<0>(buf);
#pragma unroll
        for (int x = 0; x < 8; ++x) og[(long)(x * 64 + t) * 2048] = buf[x];
    }
}

// ---------------------------------------------------------------------------
// Hermitian pointwise complex GEMM, 260 canonical frequencies, 512 threads.
// Per thread: 2 (b) x 4 (f) tile. Fill unpacks packed spectra via (k,-k);
// drain packs f-pairs via shfl.
// ---------------------------------------------------------------------------
__global__ void __launch_bounds__(512)
pointwise_kernel(const float2* __restrict__ Xp, const float2* __restrict__ Wp,
                 float2* __restrict__ Zh) {
    const int rank = blockIdx.x;
    int kx, ky, kz;
    if (rank < 192) {
        kx = 1 + rank / 64; const int r = rank & 63; ky = r >> 3; kz = r & 7;
    } else if (rank < 240) {
        const int r = rank - 192; kx = (r / 24) * 4;
        const int r2 = r % 24; ky = 1 + r2 / 8; kz = r2 & 7;
    } else {
        const int r = rank - 240; kx = (r / 10) * 4;
        const int r2 = r % 10; ky = (r2 / 5) * 4; kz = r2 % 5;
    }
    const int k = (kx << 6) | (ky << 3) | kz;
    const int neg = (((8 - kx) & 7) << 6) | (((8 - ky) & 7) << 3) | ((8 - kz) & 7);

    extern __shared__ float2 sm[];
    float2* As = sm;            // [c][b], stride 65
    float2* Bs = sm + 64 * 65;  // [c][f], stride 65
    const int tid = threadIdx.x;

    const float2* xk = Xp + (long)k * 2048;
    const float2* xn = Xp + (long)neg * 2048;
    const float2* wk = Wp + (long)k * 2048;
    const float2* wn = Wp + (long)neg * 2048;
    for (int i = tid; i < 2048; i += 512) {
        const int j = i & 31, rowi = i >> 5;
        const int c0 = 2 * j, c1 = 2 * j + 1;
        {
            const float2 Pk = xk[i], Pn = xn[i];
            As[c0 * 65 + rowi] = make_float2(0.5f * (Pk.x + Pn.x), 0.5f * (Pk.y - Pn.y));
            As[c1 * 65 + rowi] = make_float2(0.5f * (Pk.y + Pn.y), 0.5f * (Pn.x - Pk.x));
        }
        {
            const float2 Pk = wk[i], Pn = wn[i];
            Bs[c0 * 65 + rowi] = make_float2(0.5f * (Pk.x + Pn.x), 0.5f * (Pk.y - Pn.y));
            Bs[c1 * 65 + rowi] = make_float2(0.5f * (Pk.y + Pn.y), 0.5f * (Pn.x - Pk.x));
        }
    }
    __syncthreads();

    const int ft = tid & 15;   // f = ft + 16j
    const int bt = tid >> 4;   // b = bt + 32i, bt in 0..31
    unsigned long long acc[2][4];
#pragma unroll
    for (int i = 0; i < 2; ++i)
#pragma unroll
        for (int j = 0; j < 4; ++j) acc[i][j] = 0ULL;

    unsigned long long axax[2], nay[2], bxy[4], byx[4];
#pragma unroll 2
    for (int cc = 0; cc < 64; ++cc) {
#pragma unroll
        for (int i = 0; i < 2; ++i) {
            const float2 t = As[cc * 65 + bt + 32 * i];
            axax[i] = pack2(t.x, t.x);
            nay[i] = pack2(-t.y, t.y);
        }
#pragma unroll
        for (int j = 0; j < 4; ++j) {
            const float2 t = Bs[cc * 65 + ft + 16 * j];
            bxy[j] = pack2(t.x, t.y);
            byx[j] = pack2(t.y, t.x);
        }
#pragma unroll
        for (int i = 0; i < 2; ++i)
#pragma unroll
            for (int j = 0; j < 4; ++j) {
                acc[i][j] = fma2(axax[i], bxy[j], acc[i][j]);  // (+ax*bx, +ax*by)
                acc[i][j] = fma2(nay[i], byx[j], acc[i][j]);   // (-ay*by, +ay*bx)
            }
    }

    // Drain: pack f-pairs. Even-ft lanes own fp = ft/2 + 8j.
    float2* zk = Zh + (long)k * 2048;
    float2* zn = Zh + (long)neg * 2048;
    const bool self = (k == neg);
    const bool even = (ft & 1) == 0;
    const int fp0 = ft >> 1;
#pragma unroll
    for (int i = 0; i < 2; ++i)
#pragma unroll
        for (int j = 0; j < 4; ++j) {
            const unsigned long long part = __shfl_xor_sync(0xffffffffu, acc[i][j], 1);
            if (even) {
                const float2 Y0 = unpack2(acc[i][j]);  // f = 2fp
                const float2 Y1 = unpack2(part);       // f = 2fp+1
                const int idx = (bt + 32 * i) * 32 + fp0 + 8 * j;
                zk[idx] = make_float2(Y0.x - Y1.y, Y0.y + Y1.x);
                if (!self) zn[idx] = make_float2(Y0.x + Y1.y, Y1.x - Y0.y);
            }
        }
}

// ---------------------------------------------------------------------------
// Inverse packed FFT + bias, 16-column tiles, 512 threads. One block per
// (b, 16 fp columns). IFFT(Y_{2f} + i Y_{2f+1}) = out_{2f} + i out_{2f+1}.
// ---------------------------------------------------------------------------
__global__ void __launch_bounds__(512)
ifft3d_packed(const float2* __restrict__ Zh, const float* __restrict__ bias,
              float* __restrict__ out) {
    extern __shared__ float2 V[];
    const int b = blockIdx.x >> 1, fp0 = (blockIdx.x & 1) * 16;
    const int tid = threadIdx.x;
    const int c = tid & 15, pp = tid >> 4;
    const float2 bv = ((const float2*)bias)[fp0 + c];

    const float2* yg = Zh + b * 32 + fp0 + c;
    float2 buf[8];

    // Phase 1: z-axis fused with load.
#pragma unroll
    for (int m = 0; m < 2; ++m) {
        const int t = pp + 32 * m;
#pragma unroll
        for (int z = 0; z < 8; ++z) buf[z] = yg[(long)(8 * t + z) * 2048];
        fft8<1>(buf);
#pragma unroll
        for (int z = 0; z < 8; ++z) V[(8 * t + z) * 16 + c] = buf[z];
    }
    __syncthreads();

    // Phase 2: y-axis.
#pragma unroll
    for (int m = 0; m < 2; ++m) {
        const int t = pp + 32 * m;
        const int b0 = ((t >> 3) * 64 + (t & 7)) * 16 + c;
#pragma unroll
        for (int y = 0; y < 8; ++y) buf[y] = V[b0 + y * 128];
        fft8<1>(buf);
#pragma unroll
        for (int y = 0; y < 8; ++y) V[b0 + y * 128] = buf[y];
    }
    __syncthreads();

    // Phase 3: x-axis fused with store (re -> 2fp, im -> 2fp+1, +bias).
    float2* og = (float2*)out + (long)b * 512 * 32 + fp0 + c;
#pragma unroll
    for (int m = 0; m < 2; ++m) {
        const int t = pp + 32 * m;
#pragma unroll
        for (int x = 0; x < 8; ++x) buf[x] = V[t * 16 + c + x * 1024];
        fft8<1>(buf);
#pragma unroll
        for (int x = 0; x < 8; ++x)
            og[(long)(x * 64 + t) * 32] =
                make_float2(buf[x].x * (1.f / 512.f) + bv.x,
                            buf[x].y * (1.f / 512.f) + bv.y);
    }
}

// ---------------------------------------------------------------------------
extern "C" void kernel_launch(void* const* d_in, const int* in_sizes, int n_in,
                              void* d_out, int out_size) {
    const float* inputs = (const float*)d_in[0];
    const float* kern   = (const float*)d_in[1];
    const float* bias   = (const float*)d_in[2];
    float* out = (float*)d_out;

    float2 *Xp, *Wp, *Zh;
    cudaGetSymbolAddress((void**)&Xp, g_Xp);
    cudaGetSymbolAddress((void**)&Wp, g_Wp);
    cudaGetSymbolAddress((void**)&Zh, g_Z);

    const int smemFFT = 512 * 16 * (int)sizeof(float2);    // 65536 B
    const int smemPW  = 2 * 64 * 65 * (int)sizeof(float2); // 66560 B
    cudaFuncSetAttribute(fft3d_fwd_packed, cudaFuncAttributeMaxDynamicSharedMemorySize, smemFFT);
    cudaFuncSetAttribute(ifft3d_packed,    cudaFuncAttributeMaxDynamicSharedMemorySize, smemFFT);
    cudaFuncSetAttribute(pointwise_kernel, cudaFuncAttributeMaxDynamicSharedMemorySize, smemPW);

    fft3d_fwd_packed<<<256, 512, smemFFT>>>(inputs, kern, Xp, Wp);
    pointwise_kernel<<<260, 512, smemPW>>>(Xp, Wp, Zh);
    ifft3d_packed<<<128, 512, smemFFT>>>(Zh, bias, out);
}